// round 9
// baseline (speedup 1.0000x reference)
#include <cuda_runtime.h>
#include <cstdint>

// EmbedWeighted == out(B,D) = inputs(B,V) @ embeddings(V,D), pure fp32 FFMA2 GEMM
#define B_DIM 2048
#define V_DIM 2000
#define D_DIM 64
#define NSPLIT 16
#define KSPLIT 128            // splits 0..14: 128; split 15: 80 (zero-filled to 96)
#define KC 32                 // k per pipeline stage
#define NTHREADS 256
#define MTILE 128
#define NMTILE (B_DIM / MTILE)            // 16
#define A_STR 36              // words/row; a-loads <=2-way conflict
#define E_STR 68              // words/row; 16B-aligned rows, e-loads <=2-way
#define ABUF (MTILE * A_STR)              // 4608 words
#define EBUF (KC * E_STR)                 // 2176 words
#define DYN_BYTES ((2 * ABUF + 2 * EBUF) * 4)   // 54272 B -> 2 CTAs/SM

__device__ float g_partials[NSPLIT][B_DIM][D_DIM];   // 8 MB static scratch
__device__ unsigned g_arrive[NMTILE];                // zero-init, self-resetting
__device__ unsigned g_done[NMTILE];

static __device__ __forceinline__ uint32_t smem_u32(const void* p) {
    return (uint32_t)__cvta_generic_to_shared(p);
}
static __device__ __forceinline__ void cp_async16(uint32_t dst, const float* src, bool p) {
    int sz = p ? 16 : 0;   // src-size 0 => zero-fill 16B
    asm volatile("cp.async.cg.shared.global [%0], [%1], 16, %2;"
                 :: "r"(dst), "l"(src), "r"(sz));
}
static __device__ __forceinline__ void cp_commit() {
    asm volatile("cp.async.commit_group;");
}
template <int N> static __device__ __forceinline__ void cp_wait() {
    asm volatile("cp.async.wait_group %0;" :: "n"(N));
}
static __device__ __forceinline__ float lds_f32(uint32_t a) {
    float v; asm("ld.shared.f32 %0, [%1];" : "=f"(v) : "r"(a)); return v;
}
static __device__ __forceinline__ void lds_v2u64(uint32_t a, unsigned long long& x,
                                                 unsigned long long& y) {
    asm("ld.shared.v2.u64 {%0, %1}, [%2];" : "=l"(x), "=l"(y) : "r"(a));
}
static __device__ __forceinline__ unsigned long long splat2(float f) {
    unsigned long long r;
    asm("mov.b64 %0, {%1, %1};" : "=l"(r) : "f"(f));
    return r;
}
static __device__ __forceinline__ void ffma2(unsigned long long& acc,
                                             unsigned long long a,
                                             unsigned long long b) {
    asm("fma.rn.f32x2 %0, %1, %2, %0;" : "+l"(acc) : "l"(a), "l"(b));
}

// 256 threads; thread tile 4m x 8n. CTA tile M=128, N=64.
// grid (16, 16) = 256 CTAs, occ 2 guaranteed -> all co-resident.
__global__ __launch_bounds__(NTHREADS, 2)
void embedweighted_ffma2(const float* __restrict__ inp,
                         const float* __restrict__ emb,
                         float* __restrict__ out)
{
    extern __shared__ float smem[];
    // layout: A[2][ABUF], E[2][EBUF]
    const uint32_t sbase = smem_u32(smem);
    const uint32_t ebase0 = sbase + 2u * ABUF * 4u;

    const int ksplit = blockIdx.x;
    const int mtile  = blockIdx.y;
    const int m_base = mtile * MTILE;
    const int k_base = ksplit * KSPLIT;
    const int k_len  = (ksplit < NSPLIT - 1) ? KSPLIT : (V_DIM - (NSPLIT - 1) * KSPLIT);
    const int nstages = (k_len + KC - 1) / KC;   // 4 (last split: 3)

    const float* inpS = inp + (size_t)m_base * V_DIM + k_base;
    const float* embS = emb + (size_t)k_base * D_DIM;

    const int tid = threadIdx.x;
    const int tn  = tid & 7;          // n-octet: cols tn*8 .. +7
    const int tm  = tid >> 3;         // 0..31: rows tm*4 .. +3

    unsigned long long acc[4][4];     // [i=row][j=n-pair] f32x2
    #pragma unroll
    for (int i = 0; i < 4; i++)
        #pragma unroll
        for (int j = 0; j < 4; j++) acc[i][j] = 0ull;

    // ---- stage loaders (cheap: 6 warp-LDGSTS-instr per thread total/stage) ----
    auto loadA = [&](int s) {   // 128 x 32 floats, padded stride 36
        #pragma unroll
        for (int i = 0; i < 4; i++) {
            int idx = tid + i * NTHREADS;     // 0..1023
            int r = idx >> 3, q = idx & 7;    // row, float4-quad
            int k = s * KC + q * 4;
            bool p = (k < k_len);             // k_len mult of 16 -> chunk-granular
            cp_async16(sbase + (uint32_t)((s & 1) * ABUF + r * A_STR + q * 4) * 4u,
                       inpS + (size_t)r * V_DIM + (p ? k : 0), p);
        }
    };
    auto loadE = [&](int s) {   // 32 x 64 floats, padded stride 68
        #pragma unroll
        for (int i = 0; i < 2; i++) {
            int idx = tid + i * NTHREADS;     // 0..511
            int r = idx >> 4, q = idx & 15;   // k-row, float4-quad
            int k = s * KC + r;
            bool p = (k < k_len);
            cp_async16(ebase0 + (uint32_t)((s & 1) * EBUF + r * E_STR + q * 4) * 4u,
                       embS + (size_t)(p ? k : 0) * D_DIM + q * 4, p);
        }
    };

    // ---- 2-stage pipeline ----
    loadA(0); loadE(0); cp_commit();

    const uint32_t a_thr = sbase + (uint32_t)(tm * 4 * A_STR) * 4u;
    const uint32_t e_thr = ebase0 + (uint32_t)(tn * 8) * 4u;

    for (int it = 0; it < nstages; it++) {
        if (it + 1 < nstages) {
            loadA(it + 1); loadE(it + 1); cp_commit();
            cp_wait<1>();
        } else {
            cp_wait<0>();
        }
        __syncthreads();

        const uint32_t Ab = a_thr + (uint32_t)((it & 1) * ABUF) * 4u;
        const uint32_t Eb = e_thr + (uint32_t)((it & 1) * EBUF) * 4u;

        #pragma unroll 8
        for (int kk = 0; kk < KC; kk++) {
            unsigned long long av[4];
            #pragma unroll
            for (int i = 0; i < 4; i++)
                av[i] = splat2(lds_f32(Ab + (uint32_t)(i * A_STR + kk) * 4u));

            unsigned long long e0, e1, e2, e3;
            uint32_t ea = Eb + (uint32_t)(kk * E_STR) * 4u;
            lds_v2u64(ea,       e0, e1);
            lds_v2u64(ea + 16u, e2, e3);

            #pragma unroll
            for (int i = 0; i < 4; i++) {
                ffma2(acc[i][0], av[i], e0);
                ffma2(acc[i][1], av[i], e1);
                ffma2(acc[i][2], av[i], e2);
                ffma2(acc[i][3], av[i], e3);
            }
        }
        __syncthreads();   // protect buffer (it+1)&1 written next iteration
    }

    // ---- write 128x64 fp32 partial tile (f32x2 = 2 consecutive cols) ----
    {
        float* pp = &g_partials[ksplit][m_base][0];
        #pragma unroll
        for (int i = 0; i < 4; i++) {
            int row = tm * 4 + i;
            unsigned long long* dst =
                reinterpret_cast<unsigned long long*>(pp + (size_t)row * D_DIM + tn * 8);
            #pragma unroll
            for (int j = 0; j < 4; j++) dst[j] = acc[i][j];
        }
    }

    // ---- fused deterministic split-K reduction ----
    // 256 CTAs, occ 2 guaranteed (launch_bounds) -> all co-resident, spin safe.
    __syncthreads();
    if (tid == 0) {
        __threadfence();                       // release this CTA's partial stores
        atomicAdd(&g_arrive[mtile], 1u);
        unsigned v;
        do {
            asm volatile("ld.acquire.gpu.u32 %0, [%1];" : "=r"(v) : "l"(&g_arrive[mtile]));
            if (v >= NSPLIT) break;
            __nanosleep(64);
        } while (true);
    }
    __syncthreads();   // propagate tid0's acquire CTA-wide

    if (tid < 128) {   // rows [m_base + ksplit*8, +8): 128 float4
        int r = tid >> 4, q = tid & 15;
        int off = (m_base + ksplit * 8 + r) * (D_DIM / 4) + q;
        const float4* p = reinterpret_cast<const float4*>(&g_partials[0][0][0]);
        float4 s = p[off];
        #pragma unroll
        for (int sp = 1; sp < NSPLIT; sp++) {   // fixed order -> deterministic
            float4 v = p[(size_t)sp * (B_DIM * D_DIM / 4) + off];
            s.x += v.x; s.y += v.y; s.z += v.z; s.w += v.w;
        }
        reinterpret_cast<float4*>(out)[off] = s;
    }

    __syncthreads();
    if (tid == 0) {   // reset counters for graph replay
        unsigned d = atomicAdd(&g_done[mtile], 1u);
        if (d == NSPLIT - 1) {
            atomicExch(&g_arrive[mtile], 0u);
            atomicExch(&g_done[mtile], 0u);
        }
    }
}

extern "C" void kernel_launch(void* const* d_in, const int* in_sizes, int n_in,
                              void* d_out, int out_size)
{
    const float* inputs     = (const float*)d_in[0];   // (B, V) fp32
    const float* embeddings = (const float*)d_in[1];   // (V, D) fp32
    float* out = (float*)d_out;                        // (B, D) fp32

    cudaFuncSetAttribute(embedweighted_ffma2,
                         cudaFuncAttributeMaxDynamicSharedMemorySize, DYN_BYTES);

    dim3 grid(NSPLIT, NMTILE);   // 256 CTAs, occ 2 -> all co-resident
    embedweighted_ffma2<<<grid, NTHREADS, DYN_BYTES>>>(inputs, embeddings, out);
}

// round 10
// speedup vs baseline: 2.2097x; 2.2097x over previous
#include <cuda_runtime.h>
#include <cstdint>

// EmbedWeighted == out(B,D) = inputs(B,V) @ embeddings(V,D)
// fp16 m16n8k16 mma.sync (half the MMA count of tf32 k8), fp32 accum.
#define B_DIM 2048
#define V_DIM 2000
#define D_DIM 64
#define NSPLIT 16
#define KSPLIT 128            // splits 0..14: 128; split 15: 80 (zero-filled)
#define KC 32                 // k per stage (2 k16 MMA steps)
#define NTHREADS 256
#define MTILE 128
#define NMTILE (B_DIM / MTILE)            // 16
#define A_STRH 40             // halfs/row (20 words): frag banks (20g+t)%32 distinct
#define E_STRH 40

__device__ float g_partials[NSPLIT][B_DIM][D_DIM];   // 8 MB static scratch
__device__ unsigned g_arrive[NMTILE];                // zero-init, self-resetting
__device__ unsigned g_done[NMTILE];

static __device__ __forceinline__ uint32_t smem_u32(const void* p) {
    return (uint32_t)__cvta_generic_to_shared(p);
}
static __device__ __forceinline__ uint32_t lds32(uint32_t a) {
    uint32_t v; asm("ld.shared.b32 %0, [%1];" : "=r"(v) : "r"(a)); return v;
}
static __device__ __forceinline__ uint32_t pack_h2(float lo, float hi) {
    uint32_t r;   // cvt.rn.f16x2.f32 d, a, b  ->  d.hi = cvt(a), d.lo = cvt(b)
    asm("cvt.rn.f16x2.f32 %0, %1, %2;" : "=r"(r) : "f"(hi), "f"(lo));
    return r;
}

// 256 threads, 8 warps, warp tile 32m x 32n (2 mt x 4 nt). CTA tile 128x64.
// grid (16, 16) = 256 CTAs, occ 2 -> all co-resident.
__global__ __launch_bounds__(NTHREADS, 2)
void embedweighted_h16(const float* __restrict__ inp,
                       const float* __restrict__ emb,
                       float* __restrict__ out)
{
    __shared__ __align__(16) uint32_t Asm[MTILE * A_STRH / 2];   // fp16 A[m][k]
    __shared__ __align__(16) uint32_t Esm[D_DIM * E_STRH / 2];   // fp16 Et[n][k]

    const int ksplit = blockIdx.x;
    const int mtile  = blockIdx.y;
    const int m_base = mtile * MTILE;
    const int k_base = ksplit * KSPLIT;
    const int k_len  = (ksplit < NSPLIT - 1) ? KSPLIT : (V_DIM - (NSPLIT - 1) * KSPLIT);
    const int nstages = (k_len + KC - 1) / KC;   // 4 (last split: 3)

    const int tid  = threadIdx.x;
    const int warp = tid >> 5;
    const int lane = tid & 31;
    const int g = lane >> 2;          // 0..7
    const int t = lane & 3;           // 0..3
    const int warp_m = warp & 3;      // 32-row slab
    const int warp_n = warp >> 2;     // 32-col slab (0..1)

    float acc[2][4][4];
    #pragma unroll
    for (int i = 0; i < 2; i++)
        #pragma unroll
        for (int j = 0; j < 4; j++)
            #pragma unroll
            for (int r = 0; r < 4; r++) acc[i][j][r] = 0.0f;

    // -------- register prefetch buffers --------
    float4 av[4];   // A: 16 floats (4 quads)
    float  ev[8];   // E: 8 floats (one k8-column strip)
    const int en  = tid & 63;         // E n-index
    const int ekg = tid >> 6;         // E k-group (0..3) -> k = ekg*8 + i

    auto ldgA = [&](int it) {
        #pragma unroll
        for (int i = 0; i < 4; i++) {
            int idx = tid + i * NTHREADS;       // 0..1023
            int r = idx >> 3, q = idx & 7;      // row 0..127, quad 0..7
            int gk = k_base + it * KC + q * 4;
            bool p = (gk < V_DIM);              // 2000 % 4 == 0 -> quad-uniform
            const float4 v = *reinterpret_cast<const float4*>(
                inp + (size_t)(m_base + r) * V_DIM + (p ? gk : 0));
            av[i] = p ? v : make_float4(0.f, 0.f, 0.f, 0.f);
        }
    };
    auto ldgE = [&](int it) {
        int kk0 = k_base + it * KC + ekg * 8;
        #pragma unroll
        for (int i = 0; i < 8; i++) {
            int gk = kk0 + i;
            bool p = (gk < V_DIM);
            float v = __ldg(emb + (size_t)(p ? gk : 0) * D_DIM + en);
            ev[i] = p ? v : 0.f;
        }
    };
    auto stsStage = [&]() {
        const uint32_t ab = smem_u32(Asm);
        #pragma unroll
        for (int i = 0; i < 4; i++) {
            int idx = tid + i * NTHREADS;
            int r = idx >> 3, q = idx & 7;
            uint32_t h0 = pack_h2(av[i].x, av[i].y);
            uint32_t h1 = pack_h2(av[i].z, av[i].w);
            uint32_t a = ab + (uint32_t)(r * A_STRH + q * 4) * 2u;
            asm volatile("st.shared.v2.b32 [%0], {%1,%2};"
                         :: "r"(a), "r"(h0), "r"(h1) : "memory");
        }
        const uint32_t eb = smem_u32(Esm);
        uint32_t e0 = pack_h2(ev[0], ev[1]);
        uint32_t e1 = pack_h2(ev[2], ev[3]);
        uint32_t e2 = pack_h2(ev[4], ev[5]);
        uint32_t e3 = pack_h2(ev[6], ev[7]);
        uint32_t a = eb + (uint32_t)(en * E_STRH + ekg * 8) * 2u;
        asm volatile("st.shared.v4.b32 [%0], {%1,%2,%3,%4};"
                     :: "r"(a), "r"(e0), "r"(e1), "r"(e2), "r"(e3) : "memory");
    };

    auto compute = [&]() {
        const uint32_t ab = smem_u32(Asm);
        const uint32_t eb = smem_u32(Esm);
        #pragma unroll
        for (int ks = 0; ks < 2; ks++) {        // k16 steps, kk = ks*16
            uint32_t a[2][4], b[4][2];
            #pragma unroll
            for (int mt = 0; mt < 2; mt++) {
                uint32_t r0 = (uint32_t)(warp_m * 32 + mt * 16 + g);
                uint32_t b0 = ab + (r0 * A_STRH + (uint32_t)(ks * 16 + 2 * t)) * 2u;
                uint32_t b1 = b0 + 8u * A_STRH * 2u;
                a[mt][0] = lds32(b0);
                a[mt][1] = lds32(b1);
                a[mt][2] = lds32(b0 + 16u);     // k + 8
                a[mt][3] = lds32(b1 + 16u);
            }
            #pragma unroll
            for (int nt = 0; nt < 4; nt++) {
                uint32_t col = (uint32_t)(warp_n * 32 + nt * 8 + g);
                uint32_t cb = eb + (col * E_STRH + (uint32_t)(ks * 16 + 2 * t)) * 2u;
                b[nt][0] = lds32(cb);
                b[nt][1] = lds32(cb + 16u);     // k + 8
            }
            #pragma unroll
            for (int mt = 0; mt < 2; mt++)
                #pragma unroll
                for (int nt = 0; nt < 4; nt++)
                    asm volatile(
                        "mma.sync.aligned.m16n8k16.row.col.f32.f16.f16.f32 "
                        "{%0,%1,%2,%3}, {%4,%5,%6,%7}, {%8,%9}, {%0,%1,%2,%3};"
                        : "+f"(acc[mt][nt][0]), "+f"(acc[mt][nt][1]),
                          "+f"(acc[mt][nt][2]), "+f"(acc[mt][nt][3])
                        : "r"(a[mt][0]), "r"(a[mt][1]), "r"(a[mt][2]), "r"(a[mt][3]),
                          "r"(b[nt][0]), "r"(b[nt][1]));
        }
    };

    // -------- pipeline: register-prefetch it+1 while computing it --------
    ldgA(0); ldgE(0);
    stsStage();
    __syncthreads();
    for (int it = 0; it < nstages; it++) {
        if (it + 1 < nstages) { ldgA(it + 1); ldgE(it + 1); }
        compute();
        __syncthreads();               // all reads of stage it done
        if (it + 1 < nstages) {
            stsStage();
            __syncthreads();           // stage it+1 visible
        }
    }

    // -------- write 128x64 fp32 partial tile --------
    float* pp = &g_partials[ksplit][m_base][0];
    #pragma unroll
    for (int mt = 0; mt < 2; mt++) {
        int m0 = warp_m * 32 + mt * 16;
        #pragma unroll
        for (int nt = 0; nt < 4; nt++) {
            int n0 = warp_n * 32 + nt * 8 + 2 * t;
            pp[(m0 + g)     * D_DIM + n0]     = acc[mt][nt][0];
            pp[(m0 + g)     * D_DIM + n0 + 1] = acc[mt][nt][1];
            pp[(m0 + g + 8) * D_DIM + n0]     = acc[mt][nt][2];
            pp[(m0 + g + 8) * D_DIM + n0 + 1] = acc[mt][nt][3];
        }
    }

    // -------- fused deterministic split-K reduction --------
    // 256 CTAs, occ 2 (launch_bounds, 15.4 KB smem) -> all co-resident.
    __syncthreads();
    if (tid == 0) {
        __threadfence();                       // release partial stores
        atomicAdd(&g_arrive[mtile], 1u);
        unsigned v;
        do {
            asm volatile("ld.acquire.gpu.u32 %0, [%1];" : "=r"(v) : "l"(&g_arrive[mtile]));
            if (v >= NSPLIT) break;
            __nanosleep(64);
        } while (true);
    }
    __syncthreads();   // propagate tid0's acquire CTA-wide

    if (tid < 128) {   // rows [m_base + ksplit*8, +8): 128 float4
        int r = tid >> 4, q = tid & 15;
        int off = (m_base + ksplit * 8 + r) * (D_DIM / 4) + q;
        const float4* p = reinterpret_cast<const float4*>(&g_partials[0][0][0]);
        float4 s = p[off];
        #pragma unroll
        for (int sp = 1; sp < NSPLIT; sp++) {   // fixed order -> deterministic
            float4 v = p[(size_t)sp * (B_DIM * D_DIM / 4) + off];
            s.x += v.x; s.y += v.y; s.z += v.z; s.w += v.w;
        }
        reinterpret_cast<float4*>(out)[off] = s;
    }

    __syncthreads();
    if (tid == 0) {   // reset counters for graph replay
        unsigned d = atomicAdd(&g_done[mtile], 1u);
        if (d == NSPLIT - 1) {
            atomicExch(&g_arrive[mtile], 0u);
            atomicExch(&g_done[mtile], 0u);
        }
    }
}

extern "C" void kernel_launch(void* const* d_in, const int* in_sizes, int n_in,
                              void* d_out, int out_size)
{
    const float* inputs     = (const float*)d_in[0];   // (B, V) fp32
    const float* embeddings = (const float*)d_in[1];   // (V, D) fp32
    float* out = (float*)d_out;                        // (B, D) fp32

    dim3 grid(NSPLIT, NMTILE);   // 256 CTAs, occ 2 -> all co-resident
    embedweighted_h16<<<grid, NTHREADS>>>(inputs, embeddings, out);
}